// round 4
// baseline (speedup 1.0000x reference)
#include <cuda_runtime.h>
#include <cuda_bf16.h>
#include <cstdint>

#define NN    50000
#define EE    640000
#define DINN  128
#define DH    256
#define DOUTK 128

// ===================== scratch =============================================
__device__ int   g_deg[NN];
__device__ float g_invc[NN];
__device__ int   g_rowstart[NN + 1];
__device__ int   g_cursor[NN];
__device__ int   g_csr[EE];
__device__ __align__(256) float g_T[(size_t)NN * DH];
__device__ __align__(256) float g_S[(size_t)NN * DH];
__device__ __align__(256) float g_H[(size_t)NN * DH];

// packed A operands: uint2 per k-pair = (bf16x2 hi, bf16x2 lo)
__device__ __align__(256) uint2 gP1[(size_t)NN * 128];
__device__ __align__(256) uint2 gP2[(size_t)NN * 128];

// packed B (weights), [n][kpair] interleaved hi/lo
__device__ __align__(256) uint2 gB1[256 * 128];
__device__ __align__(256) uint2 gBsk[256 * 64];
__device__ __align__(256) uint2 gB2[256 * 256];
__device__ __align__(256) uint2 gB3[256 * 128];

__device__ __forceinline__ const uint2* resolve_bw(int id) {
  switch (id) {
    case 1: return gB1;
    case 2: return gBsk;
    case 3: return gB2;
    default: return gB3;
  }
}
__device__ __forceinline__ uint2* resolve_bw_mut(int id) {
  switch (id) {
    case 1: return gB1;
    case 2: return gBsk;
    case 3: return gB2;
    default: return gB3;
  }
}

__device__ __forceinline__ uint2 pack_pair(float f0, float f1) {
  __nv_bfloat16 h0 = __float2bfloat16(f0);
  __nv_bfloat16 h1 = __float2bfloat16(f1);
  __nv_bfloat16 l0 = __float2bfloat16(f0 - __bfloat162float(h0));
  __nv_bfloat16 l1 = __float2bfloat16(f1 - __bfloat162float(h1));
  uint2 u;
  u.x = (uint32_t)__bfloat16_as_ushort(h0) | ((uint32_t)__bfloat16_as_ushort(h1) << 16);
  u.y = (uint32_t)__bfloat16_as_ushort(l0) | ((uint32_t)__bfloat16_as_ushort(l1) << 16);
  return u;
}

// ===================== CSR build ===========================================
__global__ void zero_deg_kernel() {
  int i = blockIdx.x * blockDim.x + threadIdx.x;
  if (i < NN) g_deg[i] = 0;
}
__global__ void count_kernel(const int* __restrict__ dst) {
  int e = blockIdx.x * blockDim.x + threadIdx.x;
  if (e < EE) atomicAdd(&g_deg[dst[e]], 1);
}
__global__ void scan_kernel() {
  constexpr int T = 1024;
  constexpr int CHUNK = (NN + T - 1) / T;
  __shared__ int sums[T];
  const int tid = threadIdx.x;
  const int start = tid * CHUNK;
  const int end = (start + CHUNK < NN) ? (start + CHUNK) : NN;
  int s = 0;
  for (int i = start; i < end; ++i) s += g_deg[i];
  sums[tid] = s;
  __syncthreads();
  for (int off = 1; off < T; off <<= 1) {
    int v = 0;
    if (tid >= off) v = sums[tid - off];
    __syncthreads();
    if (tid >= off) sums[tid] += v;
    __syncthreads();
  }
  int run = (tid == 0) ? 0 : sums[tid - 1];
  for (int i = start; i < end; ++i) {
    const int d = g_deg[i];
    g_rowstart[i] = run;
    g_cursor[i]   = run;
    g_invc[i]     = 1.0f / (float)(d > 1 ? d : 1);
    run += d;
  }
  if (end == NN) g_rowstart[NN] = run;
}
__global__ void fill_kernel(const int* __restrict__ src, const int* __restrict__ dst) {
  int e = blockIdx.x * blockDim.x + threadIdx.x;
  if (e < EE) {
    int pos = atomicAdd(&g_cursor[dst[e]], 1);
    g_csr[pos] = src[e];
  }
}

// ===================== pack x ==============================================
__global__ void pack_x_kernel(const float* __restrict__ x) {
  int idx = blockIdx.x * blockDim.x + threadIdx.x;
  if (idx >= NN * 32) return;                // 32 float4 per row (DIN=128)
  float4 v = ((const float4*)x)[idx];
  uint2 p0 = pack_pair(v.x, v.y);
  uint2 p1 = pack_pair(v.z, v.w);
  uint4 u = make_uint4(p0.x, p0.y, p1.x, p1.y);
  ((uint4*)gP2)[idx] = u;                    // row stride 64 pairs = 32 uint4
}

// ===================== weight prep =========================================
__global__ void prep_w(const float* __restrict__ W, int N, int Kp, int bid,
                       int KpB, int pOff, int nOff) {
  int idx = blockIdx.x * blockDim.x + threadIdx.x;
  if (idx >= N * Kp) return;
  int n = idx / Kp, p = idx % Kp;
  float f0 = W[(size_t)(2 * p) * N + n];
  float f1 = W[(size_t)(2 * p + 1) * N + n];
  uint2* Bp = resolve_bw_mut(bid);
  Bp[(size_t)(nOff + n) * KpB + pOff + p] = pack_pair(f0, f1);
}

// ===================== mean aggregation (packed output) ====================
// one warp per node; output packed hi/lo into gP1 (stride D/2 pairs)
template <int D>
__global__ void agg_kernel(const float* Xp) {
  const float* __restrict__ X = Xp ? Xp : g_H;
  const int warp = (blockIdx.x * blockDim.x + threadIdx.x) >> 5;
  if (warp >= NN) return;
  const int lane = threadIdx.x & 31;
  constexpr int V = D / 128;
  float4 acc[V];
#pragma unroll
  for (int v = 0; v < V; ++v) acc[v] = make_float4(0.f, 0.f, 0.f, 0.f);
  const int beg = g_rowstart[warp];
  const int end = g_rowstart[warp + 1];
  int i = beg;
  for (; i + 4 <= end; i += 4) {
    const int s0 = g_csr[i], s1 = g_csr[i + 1], s2 = g_csr[i + 2], s3 = g_csr[i + 3];
    const float4* r0 = (const float4*)(X + (size_t)s0 * D);
    const float4* r1 = (const float4*)(X + (size_t)s1 * D);
    const float4* r2 = (const float4*)(X + (size_t)s2 * D);
    const float4* r3 = (const float4*)(X + (size_t)s3 * D);
#pragma unroll
    for (int v = 0; v < V; ++v) {
      float4 t0 = r0[lane + 32 * v];
      float4 t1 = r1[lane + 32 * v];
      float4 t2 = r2[lane + 32 * v];
      float4 t3 = r3[lane + 32 * v];
      acc[v].x += (t0.x + t1.x) + (t2.x + t3.x);
      acc[v].y += (t0.y + t1.y) + (t2.y + t3.y);
      acc[v].z += (t0.z + t1.z) + (t2.z + t3.z);
      acc[v].w += (t0.w + t1.w) + (t2.w + t3.w);
    }
  }
  for (; i < end; ++i) {
    const int s = g_csr[i];
    const float4* row = (const float4*)(X + (size_t)s * D);
#pragma unroll
    for (int v = 0; v < V; ++v) {
      float4 t = row[lane + 32 * v];
      acc[v].x += t.x; acc[v].y += t.y; acc[v].z += t.z; acc[v].w += t.w;
    }
  }
  const float ic = g_invc[warp];
  uint4* o = (uint4*)gP1 + (size_t)warp * (D / 4);
#pragma unroll
  for (int v = 0; v < V; ++v) {
    uint2 p0 = pack_pair(acc[v].x * ic, acc[v].y * ic);
    uint2 p1 = pack_pair(acc[v].z * ic, acc[v].w * ic);
    o[lane + 32 * v] = make_uint4(p0.x, p0.y, p1.x, p1.y);
  }
}

// final layer: out = mean_agg(T[:,0:128]) + T[:,128:256] + b3l
__global__ void agg_final_kernel(const float* __restrict__ b3l, float* __restrict__ out) {
  const int warp = (blockIdx.x * blockDim.x + threadIdx.x) >> 5;
  if (warp >= NN) return;
  const int lane = threadIdx.x & 31;
  float4 acc = make_float4(0.f, 0.f, 0.f, 0.f);
  const int beg = g_rowstart[warp];
  const int end = g_rowstart[warp + 1];
  int i = beg;
  for (; i + 4 <= end; i += 4) {
    const int s0 = g_csr[i], s1 = g_csr[i + 1], s2 = g_csr[i + 2], s3 = g_csr[i + 3];
    float4 t0 = *(const float4*)(g_T + (size_t)s0 * DH + lane * 4);
    float4 t1 = *(const float4*)(g_T + (size_t)s1 * DH + lane * 4);
    float4 t2 = *(const float4*)(g_T + (size_t)s2 * DH + lane * 4);
    float4 t3 = *(const float4*)(g_T + (size_t)s3 * DH + lane * 4);
    acc.x += (t0.x + t1.x) + (t2.x + t3.x);
    acc.y += (t0.y + t1.y) + (t2.y + t3.y);
    acc.z += (t0.z + t1.z) + (t2.z + t3.z);
    acc.w += (t0.w + t1.w) + (t2.w + t3.w);
  }
  for (; i < end; ++i) {
    const int s = g_csr[i];
    float4 t = *(const float4*)(g_T + (size_t)s * DH + lane * 4);
    acc.x += t.x; acc.y += t.y; acc.z += t.z; acc.w += t.w;
  }
  const float ic = g_invc[warp];
  float4 z = *(const float4*)(g_T + (size_t)warp * DH + 128 + lane * 4);
  float4 b = *(const float4*)(b3l + lane * 4);
  float4 r;
  r.x = acc.x * ic + z.x + b.x;
  r.y = acc.y * ic + z.y + b.y;
  r.z = acc.z * ic + z.z + b.z;
  r.w = acc.w * ic + z.w + b.w;
  *(float4*)(out + (size_t)warp * DOUTK + lane * 4) = r;
}

// ===================== SMEM-free bf16 MMA GEMM =============================
// C[M=50000, 256] = A @ B^T (+bias), compensated (3 passes, fp32 accum).
// A: packed uint2 (hi,lo) per k-pair, two row-major sources concat along K.
// B: packed uint2 [n][kpair]. Fragments loaded directly via coalesced LDG.64.
// CTA tile 128x128; 8 warps = 4M x 2N; warp tile 32x64 (2 mt x 8 nt).

__device__ __forceinline__ void mma_bf16(float* d, const uint32_t* a,
                                         const uint32_t* b) {
  asm volatile(
      "mma.sync.aligned.m16n8k16.row.col.f32.bf16.bf16.f32 "
      "{%0,%1,%2,%3}, {%4,%5,%6,%7}, {%8,%9}, {%0,%1,%2,%3};"
      : "+f"(d[0]), "+f"(d[1]), "+f"(d[2]), "+f"(d[3])
      : "r"(a[0]), "r"(a[1]), "r"(a[2]), "r"(a[3]), "r"(b[0]), "r"(b[1]));
}

__global__ void __launch_bounds__(256, 1)
gemm_mma(int a1id, int Kp1, int Kp2, int bid, const float* __restrict__ bias,
         int cid) {
  const int tid = threadIdx.x;
  const int wid = tid >> 5;
  const int lane = tid & 31;
  const int warpM = wid >> 1;   // 0..3
  const int warpN = wid & 1;    // 0..1
  const int rowTile = blockIdx.x * 128;
  const int colTile = blockIdx.y * 128;

  const uint2* __restrict__ A1 = (a1id == 1) ? gP1 : gP2;
  const uint2* __restrict__ A2 = gP2;
  const uint2* __restrict__ B = resolve_bw(bid);
  const int KpB = Kp1 + Kp2;

  const int r0 = lane >> 2;     // 0..7
  const int pq = lane & 3;      // 0..3

  // clamped A row indices (rows >= NN read row NN-1; results discarded)
  int rowA[2][2];
#pragma unroll
  for (int mt = 0; mt < 2; ++mt) {
    int rb = rowTile + warpM * 32 + mt * 16 + r0;
    rowA[mt][0] = (rb < NN) ? rb : (NN - 1);
    rowA[mt][1] = (rb + 8 < NN) ? (rb + 8) : (NN - 1);
  }
  // B row pointers (cols always < 256)
  const uint2* bPtr[8];
#pragma unroll
  for (int nt = 0; nt < 8; ++nt) {
    const int n = colTile + warpN * 64 + nt * 8 + r0;
    bPtr[nt] = B + (size_t)n * KpB + pq;
  }

  float acc[2][8][4];
#pragma unroll
  for (int mt = 0; mt < 2; ++mt)
#pragma unroll
    for (int nt = 0; nt < 8; ++nt)
#pragma unroll
      for (int r = 0; r < 4; ++r) acc[mt][nt][r] = 0.f;

  const int nks = KpB >> 3;
#pragma unroll 2
  for (int ks = 0; ks < nks; ++ks) {
    const int pb = ks * 8;
    const uint2* A;
    int pa, str;
    if (pb < Kp1) { A = A1; pa = pb;       str = Kp1; }
    else          { A = A2; pa = pb - Kp1; str = Kp2; }

    uint2 a[2][4];
#pragma unroll
    for (int mt = 0; mt < 2; ++mt) {
      const uint2* b0 = A + (size_t)rowA[mt][0] * str + pa + pq;
      const uint2* b1 = A + (size_t)rowA[mt][1] * str + pa + pq;
      a[mt][0] = b0[0];
      a[mt][1] = b1[0];
      a[mt][2] = b0[4];
      a[mt][3] = b1[4];
    }
    uint2 b[8][2];
#pragma unroll
    for (int nt = 0; nt < 8; ++nt) {
      const uint2* bb = bPtr[nt] + pb;
      b[nt][0] = bb[0];
      b[nt][1] = bb[4];
    }

    uint32_t ah[2][4], al[2][4], bh[8][2], bl[8][2];
#pragma unroll
    for (int mt = 0; mt < 2; ++mt)
#pragma unroll
      for (int j = 0; j < 4; ++j) { ah[mt][j] = a[mt][j].x; al[mt][j] = a[mt][j].y; }
#pragma unroll
    for (int nt = 0; nt < 8; ++nt)
#pragma unroll
      for (int j = 0; j < 2; ++j) { bh[nt][j] = b[nt][j].x; bl[nt][j] = b[nt][j].y; }

#pragma unroll
    for (int mt = 0; mt < 2; ++mt)
#pragma unroll
      for (int nt = 0; nt < 8; ++nt) mma_bf16(acc[mt][nt], ah[mt], bh[nt]);
#pragma unroll
    for (int mt = 0; mt < 2; ++mt)
#pragma unroll
      for (int nt = 0; nt < 8; ++nt) mma_bf16(acc[mt][nt], ah[mt], bl[nt]);
#pragma unroll
    for (int mt = 0; mt < 2; ++mt)
#pragma unroll
      for (int nt = 0; nt < 8; ++nt) mma_bf16(acc[mt][nt], al[mt], bh[nt]);
  }

  // ---- epilogue ----
  float* __restrict__ C = (cid == 1) ? g_T : g_S;
  const int r0base = rowTile + warpM * 32 + r0;
  const int cbase = colTile + warpN * 64 + pq * 2;
#pragma unroll
  for (int mt = 0; mt < 2; ++mt) {
    const int rr = r0base + mt * 16;
#pragma unroll
    for (int nt = 0; nt < 8; ++nt) {
      const int col = cbase + nt * 8;
      float2 bv = make_float2(0.f, 0.f);
      if (bias) bv = *(const float2*)(bias + col);
      if (rr < NN) {
        float2 v = make_float2(acc[mt][nt][0] + bv.x, acc[mt][nt][1] + bv.y);
        *(float2*)(C + (size_t)rr * 256 + col) = v;
      }
      if (rr + 8 < NN) {
        float2 v = make_float2(acc[mt][nt][2] + bv.x, acc[mt][nt][3] + bv.y);
        *(float2*)(C + (size_t)(rr + 8) * 256 + col) = v;
      }
    }
  }
}

// ===================== LayerNorm + ReLU + skip (packed out) ================
// layer==1: skip=g_S, writes g_H fp32 AND packed gP2
// layer==2: skip=g_H, writes packed gP2 only
__global__ void ln_kernel(const float* __restrict__ gamma,
                          const float* __restrict__ beta, int layer) {
  const int row = (blockIdx.x * blockDim.x + threadIdx.x) >> 5;
  if (row >= NN) return;
  const int lane = threadIdx.x & 31;
  const float4* t4 = (const float4*)(g_T + (size_t)row * DH);
  float4 v0 = t4[lane];
  float4 v1 = t4[lane + 32];
  float sum = v0.x + v0.y + v0.z + v0.w + v1.x + v1.y + v1.z + v1.w;
  float sq = v0.x * v0.x + v0.y * v0.y + v0.z * v0.z + v0.w * v0.w +
             v1.x * v1.x + v1.y * v1.y + v1.z * v1.z + v1.w * v1.w;
#pragma unroll
  for (int off = 16; off > 0; off >>= 1) {
    sum += __shfl_xor_sync(0xffffffffu, sum, off);
    sq  += __shfl_xor_sync(0xffffffffu, sq, off);
  }
  const float mu = sum * (1.0f / DH);
  const float var = sq * (1.0f / DH) - mu * mu;
  const float rs = rsqrtf(var + 1e-5f);

  const float* __restrict__ S = (layer == 1) ? g_S : g_H;
  const float4* g4 = (const float4*)gamma;
  const float4* b4 = (const float4*)beta;
  const float4* s4 = (const float4*)(S + (size_t)row * DH);
  uint4* p4 = (uint4*)gP2 + (size_t)row * 64;
  float4* h4 = (float4*)(g_H + (size_t)row * DH);
#pragma unroll
  for (int v = 0; v < 2; ++v) {
    float4 tv = (v == 0) ? v0 : v1;
    float4 gv = g4[lane + 32 * v];
    float4 bv = b4[lane + 32 * v];
    float4 sv = s4[lane + 32 * v];
    float4 r;
    r.x = fmaxf(0.f, (tv.x - mu) * rs * gv.x + bv.x) + sv.x;
    r.y = fmaxf(0.f, (tv.y - mu) * rs * gv.y + bv.y) + sv.y;
    r.z = fmaxf(0.f, (tv.z - mu) * rs * gv.z + bv.z) + sv.z;
    r.w = fmaxf(0.f, (tv.w - mu) * rs * gv.w + bv.w) + sv.w;
    uint2 q0 = pack_pair(r.x, r.y);
    uint2 q1 = pack_pair(r.z, r.w);
    p4[lane + 32 * v] = make_uint4(q0.x, q0.y, q1.x, q1.y);
    if (layer == 1) h4[lane + 32 * v] = r;
  }
}

// ===================== launch ==============================================
extern "C" void kernel_launch(void* const* d_in, const int* in_sizes, int n_in,
                              void* d_out, int out_size) {
  const float* x   = (const float*)d_in[0];
  const int*   ei  = (const int*)d_in[1];
  const float* W1l = (const float*)d_in[2];
  const float* b1l = (const float*)d_in[3];
  const float* W1r = (const float*)d_in[4];
  const float* g1  = (const float*)d_in[5];
  const float* be1 = (const float*)d_in[6];
  const float* Wsk = (const float*)d_in[7];
  const float* bsk = (const float*)d_in[8];
  const float* W2l = (const float*)d_in[9];
  const float* b2l = (const float*)d_in[10];
  const float* W2r = (const float*)d_in[11];
  const float* g2  = (const float*)d_in[12];
  const float* be2 = (const float*)d_in[13];
  const float* W3l = (const float*)d_in[14];
  const float* b3l = (const float*)d_in[15];
  const float* W3r = (const float*)d_in[16];
  float* out = (float*)d_out;

  const int* src = ei;
  const int* dst = ei + EE;

  const int nodeBlocks = (NN + 255) / 256;
  const int edgeBlocks = (EE + 255) / 256;
  const int warpBlocks = (NN + 7) / 8;
  const dim3 gemmGrid((NN + 127) / 128, 2);

  // CSR build
  zero_deg_kernel<<<nodeBlocks, 256>>>();
  count_kernel<<<edgeBlocks, 256>>>(dst);
  scan_kernel<<<1, 1024>>>();
  fill_kernel<<<edgeBlocks, 256>>>(src, dst);

  // input/weight packing
  pack_x_kernel<<<(NN * 32 + 255) / 256, 256>>>(x);
  prep_w<<<(256 * 64 + 255) / 256, 256>>>(W1l, 256, 64, 1, 128, 0, 0);
  prep_w<<<(256 * 64 + 255) / 256, 256>>>(W1r, 256, 64, 1, 128, 64, 0);
  prep_w<<<(256 * 64 + 255) / 256, 256>>>(Wsk, 256, 64, 2, 64, 0, 0);
  prep_w<<<(256 * 128 + 255) / 256, 256>>>(W2l, 256, 128, 3, 256, 0, 0);
  prep_w<<<(256 * 128 + 255) / 256, 256>>>(W2r, 256, 128, 3, 256, 128, 0);
  prep_w<<<(128 * 128 + 255) / 256, 256>>>(W3l, 128, 128, 4, 128, 0, 0);
  prep_w<<<(128 * 128 + 255) / 256, 256>>>(W3r, 128, 128, 4, 128, 0, 128);

  // ---- layer 1: T = agg(x)@W1l + x@W1r + b1l ; S = x@Wsk + bsk ;
  //               H = relu(LN(T)) + S  (H also packed into gP2)
  agg_kernel<128><<<warpBlocks, 256>>>(x);
  gemm_mma<<<gemmGrid, 256>>>(1, 64, 64, 1, b1l, 1);
  gemm_mma<<<gemmGrid, 256>>>(2, 64, 0, 2, bsk, 2);
  ln_kernel<<<warpBlocks, 256>>>(g1, be1, 1);

  // ---- layer 2: T = agg(H)@W2l + H@W2r + b2l ; H2 = relu(LN(T)) + H (packed)
  agg_kernel<256><<<warpBlocks, 256>>>(nullptr);
  gemm_mma<<<gemmGrid, 256>>>(1, 128, 128, 3, b2l, 1);
  ln_kernel<<<warpBlocks, 256>>>(g2, be2, 2);

  // ---- layer 3: T[:,0:128] = H2@W3l ; T[:,128:256] = H2@W3r ;
  //      out = mean_agg(T[:,0:128]) + T[:,128:256] + b3l
  gemm_mma<<<gemmGrid, 256>>>(2, 128, 0, 4, nullptr, 1);
  agg_final_kernel<<<warpBlocks, 256>>>(b3l, out);
}